// round 14
// baseline (speedup 1.0000x reference)
#include <cuda_runtime.h>
#include <cstdint>

#define NN   50000
#define EE   640000
#define DIN  128
#define DOUT 256
#define BN_EPS 1e-5f
#define MTILE 128
#define NTILES ((NN + MTILE - 1) / MTILE)   // 391
#define SROW 20                              // row stride in floats
#define SCAN_BLK 1024
#define NBLK ((NN + SCAN_BLK - 1) / SCAN_BLK)   // 49

// ---- two-tile stage layout (A rows 0..127, B rows 0..127) ----
#define TA_OFF 0
#define TB_OFF (128 * SROW)
#define STAGE2_F (2 * 128 * SROW)           // 5120 floats
#define SM2_BYTES (2 * STAGE2_F * 4)        // 40960 B

// ---------------- scratch (static __device__, no allocation) ----------------
__device__ __align__(16) float g_agg[(size_t)NN * DIN];   // 25.6 MB (stores MEAN)
__device__ __align__(16) float g_pre[(size_t)NN * DOUT];  // 51.2 MB
__device__ __align__(16) float g_xr[(size_t)NN * DOUT];   // 51.2 MB (x@Wr^T)
__device__ int   g_deg[NN];
__device__ int   g_excl[NN];
__device__ int   g_off[NN];
__device__ int   g_cur[NN];
__device__ int   g_bsum[NBLK];
__device__ int   g_csr[EE];
__device__ float g_sum[DOUT];
__device__ float g_sqsum[DOUT];
__device__ float g_scale[DOUT];
__device__ float g_shift[DOUT];
__device__ int   g_is64;

// ---------------- helpers -----------------------------------------------------
__device__ __forceinline__ float to_tf32(float v) {
    uint32_t o;
    asm("cvt.rna.tf32.f32 %0, %1;" : "=r"(o) : "f"(v));
    return __uint_as_float(o);
}
__device__ __forceinline__ void cp16(uint32_t dst, const float* src) {
    asm volatile("cp.async.cg.shared.global [%0], [%1], 16;" :: "r"(dst), "l"(src));
}
#define CP_COMMIT() asm volatile("cp.async.commit_group;" ::: "memory")
#define CP_WAIT1()  asm volatile("cp.async.wait_group 1;" ::: "memory")
#define CP_WAIT0()  asm volatile("cp.async.wait_group 0;" ::: "memory")

#define MMA_TF32(c, A0, A1, A2, A3, B0, B1)                                  \
    asm volatile(                                                            \
        "mma.sync.aligned.m16n8k8.row.col.f32.tf32.tf32.f32 "                \
        "{%0,%1,%2,%3}, {%4,%5,%6,%7}, {%8,%9}, {%0,%1,%2,%3};"              \
        : "+f"((c)[0]), "+f"((c)[1]), "+f"((c)[2]), "+f"((c)[3])             \
        : "r"(__float_as_uint(A0)), "r"(__float_as_uint(A1)),                \
          "r"(__float_as_uint(A2)), "r"(__float_as_uint(A3)),                \
          "r"(__float_as_uint(B0)), "r"(__float_as_uint(B1)))

__device__ __forceinline__ int load_dst(const void* eiv, int e) {
    return g_is64 ? (int)((const long long*)eiv)[EE + e] : ((const int*)eiv)[EE + e];
}
__device__ __forceinline__ int load_src(const void* eiv, int e) {
    return g_is64 ? (int)((const long long*)eiv)[e] : ((const int*)eiv)[e];
}

// ---------------- init: dtype detect + zero small arrays ---------------------
__global__ void k_init(const unsigned* __restrict__ ei) {
    int i = blockIdx.x * blockDim.x + threadIdx.x;
    if (i == 0) {
        unsigned acc = 0;
        #pragma unroll
        for (int k = 0; k < 8; k++) acc |= ei[2 * k + 1];
        acc |= ei[2 * EE - 1];
        g_is64 = (acc == 0u) ? 1 : 0;
    }
    int stride = gridDim.x * blockDim.x;
    for (int j = i; j < NN; j += stride) g_deg[j] = 0;
    if (i < DOUT) { g_sum[i] = 0.f; g_sqsum[i] = 0.f; }
}

// ---------------- CSR build ---------------------------------------------------
__global__ __launch_bounds__(256) void k_hist(const void* __restrict__ eiv) {
    int e = blockIdx.x * blockDim.x + threadIdx.x;
    if (e >= EE) return;
    atomicAdd(&g_deg[load_dst(eiv, e)], 1);
}

__global__ __launch_bounds__(SCAN_BLK) void k_scan1() {
    __shared__ int s[SCAN_BLK];
    int i = blockIdx.x * SCAN_BLK + threadIdx.x;
    int v = (i < NN) ? g_deg[i] : 0;
    s[threadIdx.x] = v;
    __syncthreads();
    for (int off = 1; off < SCAN_BLK; off <<= 1) {
        int t = (threadIdx.x >= off) ? s[threadIdx.x - off] : 0;
        __syncthreads();
        s[threadIdx.x] += t;
        __syncthreads();
    }
    if (i < NN) g_excl[i] = s[threadIdx.x] - v;
    if (threadIdx.x == SCAN_BLK - 1) g_bsum[blockIdx.x] = s[SCAN_BLK - 1];
}

// scan3 with inlined scan-of-block-sums
__global__ __launch_bounds__(256) void k_scan3() {
    __shared__ int sOff[64];
    int t = threadIdx.x;
    if (t < 32) {
        int v0 = (t < NBLK) ? g_bsum[t] : 0;
        int v1 = (32 + t < NBLK) ? g_bsum[32 + t] : 0;
        int s0 = v0, s1 = v1;
        #pragma unroll
        for (int off = 1; off < 32; off <<= 1) {
            int t0 = __shfl_up_sync(0xffffffffu, s0, off);
            int t1 = __shfl_up_sync(0xffffffffu, s1, off);
            if (t >= off) { s0 += t0; s1 += t1; }
        }
        int tot0 = __shfl_sync(0xffffffffu, s0, 31);
        sOff[t] = s0 - v0;
        sOff[32 + t] = tot0 + s1 - v1;
    }
    __syncthreads();
    int i = blockIdx.x * blockDim.x + threadIdx.x;
    if (i >= NN) return;
    int o = g_excl[i] + sOff[i / SCAN_BLK];
    g_off[i] = o;
    g_cur[i] = o;
}

__global__ __launch_bounds__(256) void k_fill(const void* __restrict__ eiv) {
    int e = blockIdx.x * blockDim.x + threadIdx.x;
    if (e >= EE) return;
    int d = load_dst(eiv, e);
    int pos = atomicAdd(&g_cur[d], 1);
    g_csr[pos] = load_src(eiv, e);
}

// ---------------- gather: warp per node, writes MEAN into g_agg ---------------
__global__ __launch_bounds__(256) void k_gather(const float* __restrict__ x) {
    int node = (int)((blockIdx.x * blockDim.x + threadIdx.x) >> 5);
    int lane = threadIdx.x & 31;
    if (node >= NN) return;
    int start = g_off[node];
    int deg = g_deg[node];
    float4 acc = make_float4(0.f, 0.f, 0.f, 0.f);
    int j = 0;
    for (; j + 4 <= deg; j += 4) {
        int s0 = g_csr[start + j], s1 = g_csr[start + j + 1];
        int s2 = g_csr[start + j + 2], s3 = g_csr[start + j + 3];
        float4 v0 = __ldg((const float4*)x + (size_t)s0 * 32 + lane);
        float4 v1 = __ldg((const float4*)x + (size_t)s1 * 32 + lane);
        float4 v2 = __ldg((const float4*)x + (size_t)s2 * 32 + lane);
        float4 v3 = __ldg((const float4*)x + (size_t)s3 * 32 + lane);
        acc.x += v0.x + v1.x + v2.x + v3.x;
        acc.y += v0.y + v1.y + v2.y + v3.y;
        acc.z += v0.z + v1.z + v2.z + v3.z;
        acc.w += v0.w + v1.w + v2.w + v3.w;
    }
    for (; j < deg; j++) {
        int s = g_csr[start + j];
        float4 v = __ldg((const float4*)x + (size_t)s * 32 + lane);
        acc.x += v.x; acc.y += v.y; acc.z += v.z; acc.w += v.w;
    }
    float inv = 1.0f / fmaxf((float)deg, 1.0f);
    acc.x *= inv; acc.y *= inv; acc.z *= inv; acc.w *= inv;
    ((float4*)g_agg)[(size_t)node * 32 + lane] = acc;
}

// =============================================================================
// Generic single-chain GEMM body: C = A(128 rows)@B(128 cols)^T, 2-stage cp.async
// Used by k_mma_xr / k_mma_id / k_mma_agg with different A/B/epilogue.
// =============================================================================
#define GEMM_CORE(Aptr, Bptr)                                                  \
    auto load_stage = [&](int stg, int kc) {                                   \
        uint32_t sb = sbase + stg * (STAGE2_F * 4);                            \
        _Pragma("unroll")                                                      \
        for (int j = 0; j < 4; j++) {                                          \
            int i = tid + 256 * j;                                             \
            int part = i & 3;                                                  \
            int r = (i >> 2) & 127;                                            \
            const float* src;                                                  \
            uint32_t doff;                                                     \
            if (j < 2) { int gr = min(row0 + r, NN - 1);                       \
                         src = (Aptr) + (size_t)gr * DIN;   doff = TA_OFF + r * SROW; } \
            else       { src = (Bptr) + (size_t)(col0 + r) * DIN; doff = TB_OFF + r * SROW; } \
            cp16(sb + (doff + part * 4) * 4, src + kc + part * 4);             \
        }                                                                      \
    };                                                                         \
    float acc[4][4][4];                                                        \
    _Pragma("unroll")                                                          \
    for (int mt = 0; mt < 4; mt++)                                             \
        _Pragma("unroll")                                                      \
        for (int nt = 0; nt < 4; nt++)                                         \
            _Pragma("unroll")                                                  \
            for (int q = 0; q < 4; q++) acc[mt][nt][q] = 0.f;                  \
    load_stage(0, 0);                                                          \
    CP_COMMIT();                                                               \
    for (int c = 0; c < 8; c++) {                                              \
        if (c < 7) { load_stage((c + 1) & 1, (c + 1) * 16); CP_COMMIT(); CP_WAIT1(); } \
        else       { CP_WAIT0(); }                                             \
        __syncthreads();                                                       \
        const float* st = smf + (c & 1) * STAGE2_F;                            \
        _Pragma("unroll")                                                      \
        for (int ks = 0; ks < 2; ks++) {                                       \
            const int kk = ks * 8 + t_;                                        \
            float bx[4], by[4];                                                \
            _Pragma("unroll")                                                  \
            for (int nt = 0; nt < 4; nt++) {                                   \
                int n = wn * 32 + nt * 8 + g_;                                 \
                const float* B = st + TB_OFF + n * SROW;                       \
                bx[nt] = to_tf32(B[kk]); by[nt] = to_tf32(B[kk + 4]);          \
            }                                                                  \
            _Pragma("unroll")                                                  \
            for (int mt = 0; mt < 4; mt++) {                                   \
                int r = wm * 64 + mt * 16 + g_;                                \
                const float* A = st + TA_OFF + r * SROW;                       \
                float a0 = to_tf32(A[kk]);                                     \
                float a1 = to_tf32(A[8 * SROW + kk]);                          \
                float a2 = to_tf32(A[kk + 4]);                                 \
                float a3 = to_tf32(A[8 * SROW + kk + 4]);                      \
                _Pragma("unroll")                                              \
                for (int nt = 0; nt < 4; nt++)                                 \
                    MMA_TF32(acc[mt][nt], a0, a1, a2, a3, bx[nt], by[nt]);     \
            }                                                                  \
        }                                                                      \
        __syncthreads();                                                       \
    }

#define GEMM_PROLOGUE()                                                        \
    extern __shared__ float smf[];                                             \
    uint32_t sbase = (uint32_t)__cvta_generic_to_shared(smf);                  \
    const int tid = threadIdx.x;                                               \
    const int warp = tid >> 5, lane = tid & 31;                                \
    const int wm = warp >> 2, wn = warp & 3;                                   \
    const int g_ = lane >> 2, t_ = lane & 3;                                   \
    const int row0 = blockIdx.x * MTILE;                                       \
    const int col0 = blockIdx.y * 128;

// ---------------- stream2 kernel A: g_xr = x@Wr^T -----------------------------
__global__ __launch_bounds__(256, 2) void k_mma_xr(
    const float* __restrict__ xg, const float* __restrict__ Wr)
{
    GEMM_PROLOGUE();
    GEMM_CORE(xg, Wr);
    #pragma unroll
    for (int mt = 0; mt < 4; mt++) {
        int ra = row0 + wm * 64 + mt * 16 + g_;
        int rb = ra + 8;
        #pragma unroll
        for (int nt = 0; nt < 4; nt++) {
            int col = col0 + wn * 32 + nt * 8 + 2 * t_;
            if (ra < NN)
                *(float2*)&g_xr[(size_t)ra * DOUT + col] =
                    make_float2(acc[mt][nt][0], acc[mt][nt][1]);
            if (rb < NN)
                *(float2*)&g_xr[(size_t)rb * DOUT + col] =
                    make_float2(acc[mt][nt][2], acc[mt][nt][3]);
        }
    }
}

// ---------------- stream2 kernel B: out = x@Wres^T + bres ---------------------
__global__ __launch_bounds__(256, 2) void k_mma_id(
    const float* __restrict__ xg, const float* __restrict__ Wres,
    const float* __restrict__ bres, float* __restrict__ out)
{
    GEMM_PROLOGUE();
    __shared__ float sBr[128];
    if (tid < 128) sBr[tid] = __ldg(&bres[col0 + tid]);
    GEMM_CORE(xg, Wres);
    #pragma unroll
    for (int mt = 0; mt < 4; mt++) {
        int ra = row0 + wm * 64 + mt * 16 + g_;
        int rb = ra + 8;
        #pragma unroll
        for (int nt = 0; nt < 4; nt++) {
            int lcol = wn * 32 + nt * 8 + 2 * t_;
            int col = col0 + lcol;
            float br0 = sBr[lcol], br1 = sBr[lcol + 1];
            if (ra < NN)
                *(float2*)&out[(size_t)ra * DOUT + col] =
                    make_float2(acc[mt][nt][0] + br0, acc[mt][nt][1] + br1);
            if (rb < NN)
                *(float2*)&out[(size_t)rb * DOUT + col] =
                    make_float2(acc[mt][nt][2] + br0, acc[mt][nt][3] + br1);
        }
    }
}

// ---------------- serial kernel: pre = agg@Wl^T + g_xr, fused BN stats --------
__global__ __launch_bounds__(256, 2) void k_mma_agg(
    const float* __restrict__ Wl)
{
    GEMM_PROLOGUE();
    GEMM_CORE(g_agg, Wl);

    float ps[8], pq[8];
    #pragma unroll
    for (int k = 0; k < 8; k++) { ps[k] = 0.f; pq[k] = 0.f; }

    #pragma unroll
    for (int mt = 0; mt < 4; mt++) {
        int ra = row0 + wm * 64 + mt * 16 + g_;
        int rb = ra + 8;
        bool va = ra < NN, vb = rb < NN;
        #pragma unroll
        for (int nt = 0; nt < 4; nt++) {
            int col = col0 + wn * 32 + nt * 8 + 2 * t_;
            if (va) {
                float2 xr = *(const float2*)&g_xr[(size_t)ra * DOUT + col];
                float v0 = acc[mt][nt][0] + xr.x;
                float v1 = acc[mt][nt][1] + xr.y;
                *(float2*)&g_pre[(size_t)ra * DOUT + col] = make_float2(v0, v1);
                ps[2 * nt] += v0; ps[2 * nt + 1] += v1;
                pq[2 * nt] += v0 * v0; pq[2 * nt + 1] += v1 * v1;
            }
            if (vb) {
                float2 xr = *(const float2*)&g_xr[(size_t)rb * DOUT + col];
                float v0 = acc[mt][nt][2] + xr.x;
                float v1 = acc[mt][nt][3] + xr.y;
                *(float2*)&g_pre[(size_t)rb * DOUT + col] = make_float2(v0, v1);
                ps[2 * nt] += v0; ps[2 * nt + 1] += v1;
                pq[2 * nt] += v0 * v0; pq[2 * nt + 1] += v1 * v1;
            }
        }
    }
    #pragma unroll
    for (int k = 0; k < 8; k++) {
        #pragma unroll
        for (int m = 4; m <= 16; m <<= 1) {
            ps[k] += __shfl_xor_sync(0xffffffffu, ps[k], m);
            pq[k] += __shfl_xor_sync(0xffffffffu, pq[k], m);
        }
    }
    if (g_ == 0) {
        #pragma unroll
        for (int nt = 0; nt < 4; nt++) {
            int col = col0 + wn * 32 + nt * 8 + 2 * t_;
            atomicAdd(&g_sum[col],       ps[2 * nt]);
            atomicAdd(&g_sum[col + 1],   ps[2 * nt + 1]);
            atomicAdd(&g_sqsum[col],     pq[2 * nt]);
            atomicAdd(&g_sqsum[col + 1], pq[2 * nt + 1]);
        }
    }
}

// ---------------- BN stats finalize -------------------------------------------
__global__ void k_stats(const float* __restrict__ gamma, const float* __restrict__ beta) {
    int j = threadIdx.x;
    const float invN = 1.0f / (float)NN;
    float mean = g_sum[j] * invN;
    float var = g_sqsum[j] * invN - mean * mean;
    float rstd = rsqrtf(var + BN_EPS);
    float sc = rstd * gamma[j];
    g_scale[j] = sc;
    g_shift[j] = beta[j] - mean * sc;
}

// ---------------- combine: out = relu(pre*sc+sh) + out ------------------------
__global__ __launch_bounds__(256) void k_combine(float* __restrict__ out) {
    size_t i = (size_t)blockIdx.x * blockDim.x + threadIdx.x;
    size_t stride = (size_t)gridDim.x * blockDim.x;
    const size_t total = (size_t)NN * (DOUT / 4);
    const float4* pre4 = (const float4*)g_pre;
    float4* out4 = (float4*)out;
    for (size_t j = i; j < total; j += stride) {
        int col4 = (int)(j & 63) * 4;
        float4 pv = pre4[j];
        float4 ov = out4[j];
        float4 sc = *(const float4*)&g_scale[col4];
        float4 sh = *(const float4*)&g_shift[col4];
        float4 o;
        o.x = fmaxf(pv.x * sc.x + sh.x, 0.f) + ov.x;
        o.y = fmaxf(pv.y * sc.y + sh.y, 0.f) + ov.y;
        o.z = fmaxf(pv.z * sc.z + sh.z, 0.f) + ov.z;
        o.w = fmaxf(pv.w * sc.w + sh.w, 0.f) + ov.w;
        out4[j] = o;
    }
}

// ---------------- launch ------------------------------------------------------
extern "C" void kernel_launch(void* const* d_in, const int* in_sizes, int n_in,
                              void* d_out, int out_size) {
    const float* x     = (const float*)d_in[0];
    const void*  ei    = d_in[1];
    const float* Wl    = (const float*)d_in[2];
    // d_in[3] = b_l — absorbed by BatchNorm, unused
    const float* Wr    = (const float*)d_in[4];
    const float* Wres  = (const float*)d_in[5];
    const float* bres  = (const float*)d_in[6];
    const float* gamma = (const float*)d_in[7];
    const float* beta  = (const float*)d_in[8];
    float* out = (float*)d_out;

    cudaFuncSetAttribute(k_mma_xr,  cudaFuncAttributeMaxDynamicSharedMemorySize, SM2_BYTES);
    cudaFuncSetAttribute(k_mma_id,  cudaFuncAttributeMaxDynamicSharedMemorySize, SM2_BYTES);
    cudaFuncSetAttribute(k_mma_agg, cudaFuncAttributeMaxDynamicSharedMemorySize, SM2_BYTES);

    // second stream carries both x-only GEMMs, overlapped with the CSR chain
    cudaStream_t s2;
    cudaEvent_t ev_fork, ev_xr, ev_id;
    cudaStreamCreateWithFlags(&s2, cudaStreamNonBlocking);
    cudaEventCreateWithFlags(&ev_fork, cudaEventDisableTiming);
    cudaEventCreateWithFlags(&ev_xr, cudaEventDisableTiming);
    cudaEventCreateWithFlags(&ev_id, cudaEventDisableTiming);

    dim3 g1(NTILES, 2);

    cudaEventRecord(ev_fork, 0);
    cudaStreamWaitEvent(s2, ev_fork, 0);
    k_mma_xr<<<g1, 256, SM2_BYTES, s2>>>(x, Wr);
    cudaEventRecord(ev_xr, s2);
    k_mma_id<<<g1, 256, SM2_BYTES, s2>>>(x, Wres, bres, out);
    cudaEventRecord(ev_id, s2);

    k_init<<<64, 1024>>>((const unsigned*)ei);
    k_hist<<<(EE + 255) / 256, 256>>>(ei);
    k_scan1<<<NBLK, SCAN_BLK>>>();
    k_scan3<<<(NN + 255) / 256, 256>>>();
    k_fill<<<(EE + 255) / 256, 256>>>(ei);
    k_gather<<<(NN * 32 + 255) / 256, 256>>>(x);

    cudaStreamWaitEvent(0, ev_xr, 0);
    k_mma_agg<<<g1, 256, SM2_BYTES>>>(Wl);
    k_stats<<<1, DOUT>>>(gamma, beta);

    cudaStreamWaitEvent(0, ev_id, 0);
    k_combine<<<2048, 256>>>(out);
}

// round 15
// speedup vs baseline: 1.0081x; 1.0081x over previous
#include <cuda_runtime.h>
#include <cstdint>

#define NN   50000
#define EE   640000
#define DIN  128
#define DOUT 256
#define BN_EPS 1e-5f
#define MTILE 128
#define NTILES ((NN + MTILE - 1) / MTILE)   // 391
#define SROW 20                              // row stride in floats
#define SCAN_BLK 1024
#define NBLK ((NN + SCAN_BLK - 1) / SCAN_BLK)   // 49

// ---- two-tile stage layout (A rows 0..127, B rows 0..127) ----
#define TA_OFF 0
#define TB_OFF (128 * SROW)
#define STAGE2_F (2 * 128 * SROW)           // 5120 floats
#define SM2_BYTES (2 * STAGE2_F * 4)        // 40960 B

// ---------------- scratch (static __device__, no allocation) ----------------
__device__ __align__(16) float g_agg[(size_t)NN * DIN];   // 25.6 MB (stores MEAN)
__device__ __align__(16) float g_pre[(size_t)NN * DOUT];  // 51.2 MB
__device__ __align__(16) float g_xr[(size_t)NN * DOUT];   // 51.2 MB (x@Wr^T)
__device__ int   g_deg[NN];
__device__ int   g_excl[NN];
__device__ int   g_off[NN];
__device__ int   g_cur[NN];
__device__ int   g_bsum[NBLK];
__device__ int   g_csr[EE];
__device__ float g_sum[DOUT];
__device__ float g_sqsum[DOUT];
__device__ float g_scale[DOUT];
__device__ float g_shift[DOUT];
__device__ int   g_is64;

// ---------------- helpers -----------------------------------------------------
__device__ __forceinline__ float to_tf32(float v) {
    uint32_t o;
    asm("cvt.rna.tf32.f32 %0, %1;" : "=r"(o) : "f"(v));
    return __uint_as_float(o);
}
__device__ __forceinline__ void cp16(uint32_t dst, const float* src) {
    asm volatile("cp.async.cg.shared.global [%0], [%1], 16;" :: "r"(dst), "l"(src));
}
#define CP_COMMIT() asm volatile("cp.async.commit_group;" ::: "memory")
#define CP_WAIT1()  asm volatile("cp.async.wait_group 1;" ::: "memory")
#define CP_WAIT0()  asm volatile("cp.async.wait_group 0;" ::: "memory")

#define MMA_TF32(c, A0, A1, A2, A3, B0, B1)                                  \
    asm volatile(                                                            \
        "mma.sync.aligned.m16n8k8.row.col.f32.tf32.tf32.f32 "                \
        "{%0,%1,%2,%3}, {%4,%5,%6,%7}, {%8,%9}, {%0,%1,%2,%3};"              \
        : "+f"((c)[0]), "+f"((c)[1]), "+f"((c)[2]), "+f"((c)[3])             \
        : "r"(__float_as_uint(A0)), "r"(__float_as_uint(A1)),                \
          "r"(__float_as_uint(A2)), "r"(__float_as_uint(A3)),                \
          "r"(__float_as_uint(B0)), "r"(__float_as_uint(B1)))

__device__ __forceinline__ int load_dst(const void* eiv, int e) {
    return g_is64 ? (int)((const long long*)eiv)[EE + e] : ((const int*)eiv)[EE + e];
}
__device__ __forceinline__ int load_src(const void* eiv, int e) {
    return g_is64 ? (int)((const long long*)eiv)[e] : ((const int*)eiv)[e];
}

// ---------------- init: dtype detect + zero small arrays ---------------------
__global__ void k_init(const unsigned* __restrict__ ei) {
    int i = blockIdx.x * blockDim.x + threadIdx.x;
    if (i == 0) {
        unsigned acc = 0;
        #pragma unroll
        for (int k = 0; k < 8; k++) acc |= ei[2 * k + 1];
        acc |= ei[2 * EE - 1];
        g_is64 = (acc == 0u) ? 1 : 0;
    }
    int stride = gridDim.x * blockDim.x;
    for (int j = i; j < NN; j += stride) g_deg[j] = 0;
    if (i < DOUT) { g_sum[i] = 0.f; g_sqsum[i] = 0.f; }
}

// ---------------- CSR build ---------------------------------------------------
__global__ __launch_bounds__(256) void k_hist(const void* __restrict__ eiv) {
    int e = blockIdx.x * blockDim.x + threadIdx.x;
    if (e >= EE) return;
    atomicAdd(&g_deg[load_dst(eiv, e)], 1);
}

__global__ __launch_bounds__(SCAN_BLK) void k_scan1() {
    __shared__ int s[SCAN_BLK];
    int i = blockIdx.x * SCAN_BLK + threadIdx.x;
    int v = (i < NN) ? g_deg[i] : 0;
    s[threadIdx.x] = v;
    __syncthreads();
    for (int off = 1; off < SCAN_BLK; off <<= 1) {
        int t = (threadIdx.x >= off) ? s[threadIdx.x - off] : 0;
        __syncthreads();
        s[threadIdx.x] += t;
        __syncthreads();
    }
    if (i < NN) g_excl[i] = s[threadIdx.x] - v;
    if (threadIdx.x == SCAN_BLK - 1) g_bsum[blockIdx.x] = s[SCAN_BLK - 1];
}

// scan3 with inlined scan-of-block-sums
__global__ __launch_bounds__(256) void k_scan3() {
    __shared__ int sOff[64];
    int t = threadIdx.x;
    if (t < 32) {
        int v0 = (t < NBLK) ? g_bsum[t] : 0;
        int v1 = (32 + t < NBLK) ? g_bsum[32 + t] : 0;
        int s0 = v0, s1 = v1;
        #pragma unroll
        for (int off = 1; off < 32; off <<= 1) {
            int t0 = __shfl_up_sync(0xffffffffu, s0, off);
            int t1 = __shfl_up_sync(0xffffffffu, s1, off);
            if (t >= off) { s0 += t0; s1 += t1; }
        }
        int tot0 = __shfl_sync(0xffffffffu, s0, 31);
        sOff[t] = s0 - v0;
        sOff[32 + t] = tot0 + s1 - v1;
    }
    __syncthreads();
    int i = blockIdx.x * blockDim.x + threadIdx.x;
    if (i >= NN) return;
    int o = g_excl[i] + sOff[i / SCAN_BLK];
    g_off[i] = o;
    g_cur[i] = o;
}

__global__ __launch_bounds__(256) void k_fill(const void* __restrict__ eiv) {
    int e = blockIdx.x * blockDim.x + threadIdx.x;
    if (e >= EE) return;
    int d = load_dst(eiv, e);
    int pos = atomicAdd(&g_cur[d], 1);
    g_csr[pos] = load_src(eiv, e);
}

// ---------------- gather: warp per node, writes MEAN into g_agg ---------------
__global__ __launch_bounds__(256) void k_gather(const float* __restrict__ x) {
    int node = (int)((blockIdx.x * blockDim.x + threadIdx.x) >> 5);
    int lane = threadIdx.x & 31;
    if (node >= NN) return;
    int start = g_off[node];
    int deg = g_deg[node];
    float4 acc = make_float4(0.f, 0.f, 0.f, 0.f);
    int j = 0;
    for (; j + 4 <= deg; j += 4) {
        int s0 = g_csr[start + j], s1 = g_csr[start + j + 1];
        int s2 = g_csr[start + j + 2], s3 = g_csr[start + j + 3];
        float4 v0 = __ldg((const float4*)x + (size_t)s0 * 32 + lane);
        float4 v1 = __ldg((const float4*)x + (size_t)s1 * 32 + lane);
        float4 v2 = __ldg((const float4*)x + (size_t)s2 * 32 + lane);
        float4 v3 = __ldg((const float4*)x + (size_t)s3 * 32 + lane);
        acc.x += v0.x + v1.x + v2.x + v3.x;
        acc.y += v0.y + v1.y + v2.y + v3.y;
        acc.z += v0.z + v1.z + v2.z + v3.z;
        acc.w += v0.w + v1.w + v2.w + v3.w;
    }
    for (; j < deg; j++) {
        int s = g_csr[start + j];
        float4 v = __ldg((const float4*)x + (size_t)s * 32 + lane);
        acc.x += v.x; acc.y += v.y; acc.z += v.z; acc.w += v.w;
    }
    float inv = 1.0f / fmaxf((float)deg, 1.0f);
    acc.x *= inv; acc.y *= inv; acc.z *= inv; acc.w *= inv;
    ((float4*)g_agg)[(size_t)node * 32 + lane] = acc;
}

// =============================================================================
// Generic single-chain GEMM body: C = A(128 rows)@B(128 cols)^T, 2-stage cp.async
// Used by k_mma_xr / k_mma_id / k_mma_agg with different A/B/epilogue.
// =============================================================================
#define GEMM_CORE(Aptr, Bptr)                                                  \
    auto load_stage = [&](int stg, int kc) {                                   \
        uint32_t sb = sbase + stg * (STAGE2_F * 4);                            \
        _Pragma("unroll")                                                      \
        for (int j = 0; j < 4; j++) {                                          \
            int i = tid + 256 * j;                                             \
            int part = i & 3;                                                  \
            int r = (i >> 2) & 127;                                            \
            const float* src;                                                  \
            uint32_t doff;                                                     \
            if (j < 2) { int gr = min(row0 + r, NN - 1);                       \
                         src = (Aptr) + (size_t)gr * DIN;   doff = TA_OFF + r * SROW; } \
            else       { src = (Bptr) + (size_t)(col0 + r) * DIN; doff = TB_OFF + r * SROW; } \
            cp16(sb + (doff + part * 4) * 4, src + kc + part * 4);             \
        }                                                                      \
    };                                                                         \
    float acc[4][4][4];                                                        \
    _Pragma("unroll")                                                          \
    for (int mt = 0; mt < 4; mt++)                                             \
        _Pragma("unroll")                                                      \
        for (int nt = 0; nt < 4; nt++)                                         \
            _Pragma("unroll")                                                  \
            for (int q = 0; q < 4; q++) acc[mt][nt][q] = 0.f;                  \
    load_stage(0, 0);                                                          \
    CP_COMMIT();                                                               \
    for (int c = 0; c < 8; c++) {                                              \
        if (c < 7) { load_stage((c + 1) & 1, (c + 1) * 16); CP_COMMIT(); CP_WAIT1(); } \
        else       { CP_WAIT0(); }                                             \
        __syncthreads();                                                       \
        const float* st = smf + (c & 1) * STAGE2_F;                            \
        _Pragma("unroll")                                                      \
        for (int ks = 0; ks < 2; ks++) {                                       \
            const int kk = ks * 8 + t_;                                        \
            float bx[4], by[4];                                                \
            _Pragma("unroll")                                                  \
            for (int nt = 0; nt < 4; nt++) {                                   \
                int n = wn * 32 + nt * 8 + g_;                                 \
                const float* B = st + TB_OFF + n * SROW;                       \
                bx[nt] = to_tf32(B[kk]); by[nt] = to_tf32(B[kk + 4]);          \
            }                                                                  \
            _Pragma("unroll")                                                  \
            for (int mt = 0; mt < 4; mt++) {                                   \
                int r = wm * 64 + mt * 16 + g_;                                \
                const float* A = st + TA_OFF + r * SROW;                       \
                float a0 = to_tf32(A[kk]);                                     \
                float a1 = to_tf32(A[8 * SROW + kk]);                          \
                float a2 = to_tf32(A[kk + 4]);                                 \
                float a3 = to_tf32(A[8 * SROW + kk + 4]);                      \
                _Pragma("unroll")                                              \
                for (int nt = 0; nt < 4; nt++)                                 \
                    MMA_TF32(acc[mt][nt], a0, a1, a2, a3, bx[nt], by[nt]);     \
            }                                                                  \
        }                                                                      \
        __syncthreads();                                                       \
    }

#define GEMM_PROLOGUE()                                                        \
    extern __shared__ float smf[];                                             \
    uint32_t sbase = (uint32_t)__cvta_generic_to_shared(smf);                  \
    const int tid = threadIdx.x;                                               \
    const int warp = tid >> 5, lane = tid & 31;                                \
    const int wm = warp >> 2, wn = warp & 3;                                   \
    const int g_ = lane >> 2, t_ = lane & 3;                                   \
    const int row0 = blockIdx.x * MTILE;                                       \
    const int col0 = blockIdx.y * 128;

// ---------------- stream2 kernel A: g_xr = x@Wr^T -----------------------------
__global__ __launch_bounds__(256, 2) void k_mma_xr(
    const float* __restrict__ xg, const float* __restrict__ Wr)
{
    GEMM_PROLOGUE();
    GEMM_CORE(xg, Wr);
    #pragma unroll
    for (int mt = 0; mt < 4; mt++) {
        int ra = row0 + wm * 64 + mt * 16 + g_;
        int rb = ra + 8;
        #pragma unroll
        for (int nt = 0; nt < 4; nt++) {
            int col = col0 + wn * 32 + nt * 8 + 2 * t_;
            if (ra < NN)
                *(float2*)&g_xr[(size_t)ra * DOUT + col] =
                    make_float2(acc[mt][nt][0], acc[mt][nt][1]);
            if (rb < NN)
                *(float2*)&g_xr[(size_t)rb * DOUT + col] =
                    make_float2(acc[mt][nt][2], acc[mt][nt][3]);
        }
    }
}

// ---------------- stream2 kernel B: out = x@Wres^T + bres ---------------------
__global__ __launch_bounds__(256, 2) void k_mma_id(
    const float* __restrict__ xg, const float* __restrict__ Wres,
    const float* __restrict__ bres, float* __restrict__ out)
{
    GEMM_PROLOGUE();
    __shared__ float sBr[128];
    if (tid < 128) sBr[tid] = __ldg(&bres[col0 + tid]);
    GEMM_CORE(xg, Wres);
    #pragma unroll
    for (int mt = 0; mt < 4; mt++) {
        int ra = row0 + wm * 64 + mt * 16 + g_;
        int rb = ra + 8;
        #pragma unroll
        for (int nt = 0; nt < 4; nt++) {
            int lcol = wn * 32 + nt * 8 + 2 * t_;
            int col = col0 + lcol;
            float br0 = sBr[lcol], br1 = sBr[lcol + 1];
            if (ra < NN)
                *(float2*)&out[(size_t)ra * DOUT + col] =
                    make_float2(acc[mt][nt][0] + br0, acc[mt][nt][1] + br1);
            if (rb < NN)
                *(float2*)&out[(size_t)rb * DOUT + col] =
                    make_float2(acc[mt][nt][2] + br0, acc[mt][nt][3] + br1);
        }
    }
}

// ---------------- serial kernel: pre = agg@Wl^T + g_xr, fused BN stats --------
__global__ __launch_bounds__(256, 2) void k_mma_agg(
    const float* __restrict__ Wl)
{
    GEMM_PROLOGUE();
    GEMM_CORE(g_agg, Wl);

    float ps[8], pq[8];
    #pragma unroll
    for (int k = 0; k < 8; k++) { ps[k] = 0.f; pq[k] = 0.f; }

    #pragma unroll
    for (int mt = 0; mt < 4; mt++) {
        int ra = row0 + wm * 64 + mt * 16 + g_;
        int rb = ra + 8;
        bool va = ra < NN, vb = rb < NN;
        #pragma unroll
        for (int nt = 0; nt < 4; nt++) {
            int col = col0 + wn * 32 + nt * 8 + 2 * t_;
            if (va) {
                float2 xr = *(const float2*)&g_xr[(size_t)ra * DOUT + col];
                float v0 = acc[mt][nt][0] + xr.x;
                float v1 = acc[mt][nt][1] + xr.y;
                *(float2*)&g_pre[(size_t)ra * DOUT + col] = make_float2(v0, v1);
                ps[2 * nt] += v0; ps[2 * nt + 1] += v1;
                pq[2 * nt] += v0 * v0; pq[2 * nt + 1] += v1 * v1;
            }
            if (vb) {
                float2 xr = *(const float2*)&g_xr[(size_t)rb * DOUT + col];
                float v0 = acc[mt][nt][2] + xr.x;
                float v1 = acc[mt][nt][3] + xr.y;
                *(float2*)&g_pre[(size_t)rb * DOUT + col] = make_float2(v0, v1);
                ps[2 * nt] += v0; ps[2 * nt + 1] += v1;
                pq[2 * nt] += v0 * v0; pq[2 * nt + 1] += v1 * v1;
            }
        }
    }
    #pragma unroll
    for (int k = 0; k < 8; k++) {
        #pragma unroll
        for (int m = 4; m <= 16; m <<= 1) {
            ps[k] += __shfl_xor_sync(0xffffffffu, ps[k], m);
            pq[k] += __shfl_xor_sync(0xffffffffu, pq[k], m);
        }
    }
    if (g_ == 0) {
        #pragma unroll
        for (int nt = 0; nt < 4; nt++) {
            int col = col0 + wn * 32 + nt * 8 + 2 * t_;
            atomicAdd(&g_sum[col],       ps[2 * nt]);
            atomicAdd(&g_sum[col + 1],   ps[2 * nt + 1]);
            atomicAdd(&g_sqsum[col],     pq[2 * nt]);
            atomicAdd(&g_sqsum[col + 1], pq[2 * nt + 1]);
        }
    }
}

// ---------------- BN stats finalize -------------------------------------------
__global__ void k_stats(const float* __restrict__ gamma, const float* __restrict__ beta) {
    int j = threadIdx.x;
    const float invN = 1.0f / (float)NN;
    float mean = g_sum[j] * invN;
    float var = g_sqsum[j] * invN - mean * mean;
    float rstd = rsqrtf(var + BN_EPS);
    float sc = rstd * gamma[j];
    g_scale[j] = sc;
    g_shift[j] = beta[j] - mean * sc;
}

// ---------------- combine: out = relu(pre*sc+sh) + out ------------------------
__global__ __launch_bounds__(256) void k_combine(float* __restrict__ out) {
    size_t i = (size_t)blockIdx.x * blockDim.x + threadIdx.x;
    size_t stride = (size_t)gridDim.x * blockDim.x;
    const size_t total = (size_t)NN * (DOUT / 4);
    const float4* pre4 = (const float4*)g_pre;
    float4* out4 = (float4*)out;
    for (size_t j = i; j < total; j += stride) {
        int col4 = (int)(j & 63) * 4;
        float4 pv = pre4[j];
        float4 ov = out4[j];
        float4 sc = *(const float4*)&g_scale[col4];
        float4 sh = *(const float4*)&g_shift[col4];
        float4 o;
        o.x = fmaxf(pv.x * sc.x + sh.x, 0.f) + ov.x;
        o.y = fmaxf(pv.y * sc.y + sh.y, 0.f) + ov.y;
        o.z = fmaxf(pv.z * sc.z + sh.z, 0.f) + ov.z;
        o.w = fmaxf(pv.w * sc.w + sh.w, 0.f) + ov.w;
        out4[j] = o;
    }
}

// ---------------- launch ------------------------------------------------------
extern "C" void kernel_launch(void* const* d_in, const int* in_sizes, int n_in,
                              void* d_out, int out_size) {
    const float* x     = (const float*)d_in[0];
    const void*  ei    = d_in[1];
    const float* Wl    = (const float*)d_in[2];
    // d_in[3] = b_l — absorbed by BatchNorm, unused
    const float* Wr    = (const float*)d_in[4];
    const float* Wres  = (const float*)d_in[5];
    const float* bres  = (const float*)d_in[6];
    const float* gamma = (const float*)d_in[7];
    const float* beta  = (const float*)d_in[8];
    float* out = (float*)d_out;

    cudaFuncSetAttribute(k_mma_xr,  cudaFuncAttributeMaxDynamicSharedMemorySize, SM2_BYTES);
    cudaFuncSetAttribute(k_mma_id,  cudaFuncAttributeMaxDynamicSharedMemorySize, SM2_BYTES);
    cudaFuncSetAttribute(k_mma_agg, cudaFuncAttributeMaxDynamicSharedMemorySize, SM2_BYTES);

    // second stream carries both x-only GEMMs, overlapped with the CSR chain
    cudaStream_t s2;
    cudaEvent_t ev_fork, ev_xr, ev_id;
    cudaStreamCreateWithFlags(&s2, cudaStreamNonBlocking);
    cudaEventCreateWithFlags(&ev_fork, cudaEventDisableTiming);
    cudaEventCreateWithFlags(&ev_xr, cudaEventDisableTiming);
    cudaEventCreateWithFlags(&ev_id, cudaEventDisableTiming);

    dim3 g1(NTILES, 2);

    cudaEventRecord(ev_fork, 0);
    cudaStreamWaitEvent(s2, ev_fork, 0);
    k_mma_xr<<<g1, 256, SM2_BYTES, s2>>>(x, Wr);
    cudaEventRecord(ev_xr, s2);
    k_mma_id<<<g1, 256, SM2_BYTES, s2>>>(x, Wres, bres, out);
    cudaEventRecord(ev_id, s2);

    k_init<<<64, 1024>>>((const unsigned*)ei);
    k_hist<<<(EE + 255) / 256, 256>>>(ei);
    k_scan1<<<NBLK, SCAN_BLK>>>();
    k_scan3<<<(NN + 255) / 256, 256>>>();
    k_fill<<<(EE + 255) / 256, 256>>>(ei);
    k_gather<<<(NN * 32 + 255) / 256, 256>>>(x);

    cudaStreamWaitEvent(0, ev_xr, 0);
    k_mma_agg<<<g1, 256, SM2_BYTES>>>(Wl);
    k_stats<<<1, DOUT>>>(gamma, beta);

    cudaStreamWaitEvent(0, ev_id, 0);
    k_combine<<<2048, 256>>>(out);
}

// round 16
// speedup vs baseline: 1.1624x; 1.1531x over previous
#include <cuda_runtime.h>
#include <cstdint>

#define NN   50000
#define EE   640000
#define DIN  128
#define DOUT 256
#define BN_EPS 1e-5f
#define MTILE 128
#define NTILES ((NN + MTILE - 1) / MTILE)   // 391
#define SROW 20                              // row stride in floats
#define SCAN_BLK 1024
#define NBLK ((NN + SCAN_BLK - 1) / SCAN_BLK)   // 49

// ---- kernel1 stage layout (floats): 4 tiles of 128 rows x 16 k ----
#define AG_OFF 0
#define X_OFF  (128 * SROW)
#define WL_OFF (2 * 128 * SROW)
#define WR_OFF (3 * 128 * SROW)
#define STAGE_F (4 * 128 * SROW)            // 10240 floats
#define SM1_BYTES (2 * STAGE_F * 4)         // 81920 B

// ---- kernel2 stage layout ----
#define X2_OFF 0
#define W2_OFF (128 * SROW)
#define STAGE2_F (2 * 128 * SROW)           // 5120 floats
#define SM2_BYTES (2 * STAGE2_F * 4)        // 40960 B

// ---------------- scratch (static __device__, no allocation) ----------------
__device__ __align__(16) float g_agg[(size_t)NN * DIN];   // 25.6 MB (stores MEAN)
__device__ __align__(16) float g_pre[(size_t)NN * DOUT];  // 51.2 MB
__device__ int   g_deg[NN];
__device__ int   g_excl[NN];
__device__ int   g_off[NN];
__device__ int   g_cur[NN];
__device__ int   g_bsum[NBLK];
__device__ int   g_csr[EE];
__device__ float g_sum[DOUT];
__device__ float g_sqsum[DOUT];
__device__ int   g_is64;

// ---------------- helpers -----------------------------------------------------
__device__ __forceinline__ float to_tf32(float v) {
    uint32_t o;
    asm("cvt.rna.tf32.f32 %0, %1;" : "=r"(o) : "f"(v));
    return __uint_as_float(o);
}
__device__ __forceinline__ void cp16(uint32_t dst, const float* src) {
    asm volatile("cp.async.cg.shared.global [%0], [%1], 16;" :: "r"(dst), "l"(src));
}
#define CP_COMMIT() asm volatile("cp.async.commit_group;" ::: "memory")
#define CP_WAIT1()  asm volatile("cp.async.wait_group 1;" ::: "memory")
#define CP_WAIT0()  asm volatile("cp.async.wait_group 0;" ::: "memory")

#define MMA_TF32(c, A0, A1, A2, A3, B0, B1)                                  \
    asm volatile(                                                            \
        "mma.sync.aligned.m16n8k8.row.col.f32.tf32.tf32.f32 "                \
        "{%0,%1,%2,%3}, {%4,%5,%6,%7}, {%8,%9}, {%0,%1,%2,%3};"              \
        : "+f"((c)[0]), "+f"((c)[1]), "+f"((c)[2]), "+f"((c)[3])             \
        : "r"(__float_as_uint(A0)), "r"(__float_as_uint(A1)),                \
          "r"(__float_as_uint(A2)), "r"(__float_as_uint(A3)),                \
          "r"(__float_as_uint(B0)), "r"(__float_as_uint(B1)))

__device__ __forceinline__ int load_dst(const void* eiv, int e) {
    return g_is64 ? (int)((const long long*)eiv)[EE + e] : ((const int*)eiv)[EE + e];
}
__device__ __forceinline__ int load_src(const void* eiv, int e) {
    return g_is64 ? (int)((const long long*)eiv)[e] : ((const int*)eiv)[e];
}

// ---------------- init: dtype detect + zero small arrays ---------------------
__global__ void k_init(const unsigned* __restrict__ ei) {
    int i = blockIdx.x * blockDim.x + threadIdx.x;
    if (i == 0) {
        unsigned acc = 0;
        #pragma unroll
        for (int k = 0; k < 8; k++) acc |= ei[2 * k + 1];
        acc |= ei[2 * EE - 1];
        g_is64 = (acc == 0u) ? 1 : 0;
    }
    int stride = gridDim.x * blockDim.x;
    for (int j = i; j < NN; j += stride) g_deg[j] = 0;
    if (i < DOUT) { g_sum[i] = 0.f; g_sqsum[i] = 0.f; }
}

// ---------------- CSR build ---------------------------------------------------
// 4 edges per thread, vectorized dst loads
__global__ __launch_bounds__(256) void k_hist(const void* __restrict__ eiv) {
    int e = (blockIdx.x * blockDim.x + threadIdx.x) * 4;
    if (e >= EE) return;
    int d0, d1, d2, d3;
    if (g_is64) {
        const long long* p = (const long long*)eiv + EE + e;
        longlong2 a = *(const longlong2*)p;
        longlong2 b = *(const longlong2*)(p + 2);
        d0 = (int)a.x; d1 = (int)a.y; d2 = (int)b.x; d3 = (int)b.y;
    } else {
        int4 v = *(const int4*)((const int*)eiv + EE + e);
        d0 = v.x; d1 = v.y; d2 = v.z; d3 = v.w;
    }
    atomicAdd(&g_deg[d0], 1);
    atomicAdd(&g_deg[d1], 1);
    atomicAdd(&g_deg[d2], 1);
    atomicAdd(&g_deg[d3], 1);
}

__global__ __launch_bounds__(SCAN_BLK) void k_scan1() {
    __shared__ int s[SCAN_BLK];
    int i = blockIdx.x * SCAN_BLK + threadIdx.x;
    int v = (i < NN) ? g_deg[i] : 0;
    s[threadIdx.x] = v;
    __syncthreads();
    for (int off = 1; off < SCAN_BLK; off <<= 1) {
        int t = (threadIdx.x >= off) ? s[threadIdx.x - off] : 0;
        __syncthreads();
        s[threadIdx.x] += t;
        __syncthreads();
    }
    if (i < NN) g_excl[i] = s[threadIdx.x] - v;
    if (threadIdx.x == SCAN_BLK - 1) g_bsum[blockIdx.x] = s[SCAN_BLK - 1];
}

// scan3 with inlined scan-of-block-sums (every block redundantly scans 49 ints)
__global__ __launch_bounds__(256) void k_scan3() {
    __shared__ int sOff[64];
    int t = threadIdx.x;
    if (t < 32) {
        int v0 = (t < NBLK) ? g_bsum[t] : 0;
        int v1 = (32 + t < NBLK) ? g_bsum[32 + t] : 0;
        int s0 = v0, s1 = v1;
        #pragma unroll
        for (int off = 1; off < 32; off <<= 1) {
            int t0 = __shfl_up_sync(0xffffffffu, s0, off);
            int t1 = __shfl_up_sync(0xffffffffu, s1, off);
            if (t >= off) { s0 += t0; s1 += t1; }
        }
        int tot0 = __shfl_sync(0xffffffffu, s0, 31);
        sOff[t] = s0 - v0;
        sOff[32 + t] = tot0 + s1 - v1;
    }
    __syncthreads();
    int i = blockIdx.x * blockDim.x + threadIdx.x;
    if (i >= NN) return;
    int o = g_excl[i] + sOff[i / SCAN_BLK];
    g_off[i] = o;
    g_cur[i] = o;
}

__global__ __launch_bounds__(256) void k_fill(const void* __restrict__ eiv) {
    int e = blockIdx.x * blockDim.x + threadIdx.x;
    if (e >= EE) return;
    int d = load_dst(eiv, e);
    int pos = atomicAdd(&g_cur[d], 1);
    g_csr[pos] = load_src(eiv, e);
}

// ---------------- gather: warp per node, writes MEAN into g_agg ---------------
__global__ __launch_bounds__(256) void k_gather(const float* __restrict__ x) {
    int node = (int)((blockIdx.x * blockDim.x + threadIdx.x) >> 5);
    int lane = threadIdx.x & 31;
    if (node >= NN) return;
    int start = g_off[node];
    int deg = g_deg[node];
    float4 acc = make_float4(0.f, 0.f, 0.f, 0.f);
    int j = 0;
    for (; j + 4 <= deg; j += 4) {
        int s0 = g_csr[start + j], s1 = g_csr[start + j + 1];
        int s2 = g_csr[start + j + 2], s3 = g_csr[start + j + 3];
        float4 v0 = __ldg((const float4*)x + (size_t)s0 * 32 + lane);
        float4 v1 = __ldg((const float4*)x + (size_t)s1 * 32 + lane);
        float4 v2 = __ldg((const float4*)x + (size_t)s2 * 32 + lane);
        float4 v3 = __ldg((const float4*)x + (size_t)s3 * 32 + lane);
        acc.x += v0.x + v1.x + v2.x + v3.x;
        acc.y += v0.y + v1.y + v2.y + v3.y;
        acc.z += v0.z + v1.z + v2.z + v3.z;
        acc.w += v0.w + v1.w + v2.w + v3.w;
    }
    for (; j < deg; j++) {
        int s = g_csr[start + j];
        float4 v = __ldg((const float4*)x + (size_t)s * 32 + lane);
        acc.x += v.x; acc.y += v.y; acc.z += v.z; acc.w += v.w;
    }
    float inv = 1.0f / fmaxf((float)deg, 1.0f);
    acc.x *= inv; acc.y *= inv; acc.z *= inv; acc.w *= inv;
    ((float4*)g_agg)[(size_t)node * 32 + lane] = acc;
}

// ---------------- kernel 1: pre = agg@Wl^T + x@Wr^T + fused BN stats ---------
__global__ __launch_bounds__(256, 2) void k_mma_pre(
    const float* __restrict__ xg, const float* __restrict__ Wl,
    const float* __restrict__ Wr)
{
    extern __shared__ float smf[];
    uint32_t sbase = (uint32_t)__cvta_generic_to_shared(smf);

    const int tid = threadIdx.x;
    const int warp = tid >> 5, lane = tid & 31;
    const int wm = warp >> 2, wn = warp & 3;
    const int g_ = lane >> 2, t_ = lane & 3;
    const int row0 = blockIdx.x * MTILE;
    const int col0 = blockIdx.y * 128;

    auto load_stage = [&](int stg, int kc) {
        uint32_t sb = sbase + stg * (STAGE_F * 4);
        #pragma unroll
        for (int j = 0; j < 8; j++) {
            int i = tid + 256 * j;
            int part = i & 3;
            int r = (i >> 2) & 127;
            const float* src;
            uint32_t doff;
            if (j < 2)      { int gr = min(row0 + r, NN - 1);
                              src = g_agg + (size_t)gr * DIN;          doff = AG_OFF + r * SROW; }
            else if (j < 4) { int gr = min(row0 + r, NN - 1);
                              src = xg + (size_t)gr * DIN;             doff = X_OFF + r * SROW; }
            else if (j < 6) { src = Wl + (size_t)(col0 + r) * DIN;     doff = WL_OFF + r * SROW; }
            else            { src = Wr + (size_t)(col0 + r) * DIN;     doff = WR_OFF + r * SROW; }
            cp16(sb + (doff + part * 4) * 4, src + kc + part * 4);
        }
    };

    float acc[4][4][4];
    #pragma unroll
    for (int mt = 0; mt < 4; mt++)
        #pragma unroll
        for (int nt = 0; nt < 4; nt++)
            #pragma unroll
            for (int q = 0; q < 4; q++) acc[mt][nt][q] = 0.f;

    load_stage(0, 0);
    CP_COMMIT();

    for (int c = 0; c < 8; c++) {
        if (c < 7) { load_stage((c + 1) & 1, (c + 1) * 16); CP_COMMIT(); CP_WAIT1(); }
        else       { CP_WAIT0(); }
        __syncthreads();
        const float* st = smf + (c & 1) * STAGE_F;

        #pragma unroll
        for (int ks = 0; ks < 2; ks++) {
            const int kk = ks * 8 + t_;
            float blx[4], bly[4], brx[4], bry[4];
            #pragma unroll
            for (int nt = 0; nt < 4; nt++) {
                int n = wn * 32 + nt * 8 + g_;
                const float* B1 = st + WL_OFF + n * SROW;
                blx[nt] = to_tf32(B1[kk]); bly[nt] = to_tf32(B1[kk + 4]);
                const float* B2 = st + WR_OFF + n * SROW;
                brx[nt] = to_tf32(B2[kk]); bry[nt] = to_tf32(B2[kk + 4]);
            }
            #pragma unroll
            for (int mt = 0; mt < 4; mt++) {
                int r = wm * 64 + mt * 16 + g_;
                const float* A = st + AG_OFF + r * SROW;
                float a0 = to_tf32(A[kk]);
                float a1 = to_tf32(A[8 * SROW + kk]);
                float a2 = to_tf32(A[kk + 4]);
                float a3 = to_tf32(A[8 * SROW + kk + 4]);
                const float* X = st + X_OFF + r * SROW;
                float x0 = to_tf32(X[kk]);
                float x1 = to_tf32(X[8 * SROW + kk]);
                float x2 = to_tf32(X[kk + 4]);
                float x3 = to_tf32(X[8 * SROW + kk + 4]);
                #pragma unroll
                for (int nt = 0; nt < 4; nt++) {
                    MMA_TF32(acc[mt][nt], a0, a1, a2, a3, blx[nt], bly[nt]);
                    MMA_TF32(acc[mt][nt], x0, x1, x2, x3, brx[nt], bry[nt]);
                }
            }
        }
        __syncthreads();
    }

    // ---- epilogue: store g_pre + fused BN column stats ----
    float ps[8], pq[8];
    #pragma unroll
    for (int k = 0; k < 8; k++) { ps[k] = 0.f; pq[k] = 0.f; }

    #pragma unroll
    for (int mt = 0; mt < 4; mt++) {
        int ra = row0 + wm * 64 + mt * 16 + g_;
        int rb = ra + 8;
        bool va = ra < NN, vb = rb < NN;
        #pragma unroll
        for (int nt = 0; nt < 4; nt++) {
            int col = col0 + wn * 32 + nt * 8 + 2 * t_;
            if (va) {
                *(float2*)&g_pre[(size_t)ra * DOUT + col] =
                    make_float2(acc[mt][nt][0], acc[mt][nt][1]);
                ps[2 * nt]     += acc[mt][nt][0];
                ps[2 * nt + 1] += acc[mt][nt][1];
                pq[2 * nt]     += acc[mt][nt][0] * acc[mt][nt][0];
                pq[2 * nt + 1] += acc[mt][nt][1] * acc[mt][nt][1];
            }
            if (vb) {
                *(float2*)&g_pre[(size_t)rb * DOUT + col] =
                    make_float2(acc[mt][nt][2], acc[mt][nt][3]);
                ps[2 * nt]     += acc[mt][nt][2];
                ps[2 * nt + 1] += acc[mt][nt][3];
                pq[2 * nt]     += acc[mt][nt][2] * acc[mt][nt][2];
                pq[2 * nt + 1] += acc[mt][nt][3] * acc[mt][nt][3];
            }
        }
    }
    #pragma unroll
    for (int k = 0; k < 8; k++) {
        #pragma unroll
        for (int m = 4; m <= 16; m <<= 1) {
            ps[k] += __shfl_xor_sync(0xffffffffu, ps[k], m);
            pq[k] += __shfl_xor_sync(0xffffffffu, pq[k], m);
        }
    }
    if (g_ == 0) {
        #pragma unroll
        for (int nt = 0; nt < 4; nt++) {
            int col = col0 + wn * 32 + nt * 8 + 2 * t_;
            atomicAdd(&g_sum[col],       ps[2 * nt]);
            atomicAdd(&g_sum[col + 1],   ps[2 * nt + 1]);
            atomicAdd(&g_sqsum[col],     pq[2 * nt]);
            atomicAdd(&g_sqsum[col + 1], pq[2 * nt + 1]);
        }
    }
}

// ---------------- kernel 2: id = x@Wres^T + bres -> out (no BN dependency) ---
__global__ __launch_bounds__(256, 2) void k_mma_id(
    const float* __restrict__ xg, const float* __restrict__ Wres,
    const float* __restrict__ bres, float* __restrict__ out)
{
    extern __shared__ float smf[];
    __shared__ float sBr[128];
    uint32_t sbase = (uint32_t)__cvta_generic_to_shared(smf);

    const int tid = threadIdx.x;
    const int warp = tid >> 5, lane = tid & 31;
    const int wm = warp >> 2, wn = warp & 3;
    const int g_ = lane >> 2, t_ = lane & 3;
    const int row0 = blockIdx.x * MTILE;
    const int col0 = blockIdx.y * 128;

    if (tid < 128) sBr[tid] = __ldg(&bres[col0 + tid]);

    auto load_stage = [&](int stg, int kc) {
        uint32_t sb = sbase + stg * (STAGE2_F * 4);
        #pragma unroll
        for (int j = 0; j < 4; j++) {
            int i = tid + 256 * j;
            int part = i & 3;
            int r = (i >> 2) & 127;
            const float* src;
            uint32_t doff;
            if (j < 2) { int gr = min(row0 + r, NN - 1);
                         src = xg + (size_t)gr * DIN;             doff = X2_OFF + r * SROW; }
            else       { src = Wres + (size_t)(col0 + r) * DIN;   doff = W2_OFF + r * SROW; }
            cp16(sb + (doff + part * 4) * 4, src + kc + part * 4);
        }
    };

    float acc[4][4][4];
    #pragma unroll
    for (int mt = 0; mt < 4; mt++)
        #pragma unroll
        for (int nt = 0; nt < 4; nt++)
            #pragma unroll
            for (int q = 0; q < 4; q++) acc[mt][nt][q] = 0.f;

    load_stage(0, 0);
    CP_COMMIT();

    for (int c = 0; c < 8; c++) {
        if (c < 7) { load_stage((c + 1) & 1, (c + 1) * 16); CP_COMMIT(); CP_WAIT1(); }
        else       { CP_WAIT0(); }
        __syncthreads();
        const float* st = smf + (c & 1) * STAGE2_F;

        #pragma unroll
        for (int ks = 0; ks < 2; ks++) {
            const int kk = ks * 8 + t_;
            float bx[4], by[4];
            #pragma unroll
            for (int nt = 0; nt < 4; nt++) {
                int n = wn * 32 + nt * 8 + g_;
                const float* B = st + W2_OFF + n * SROW;
                bx[nt] = to_tf32(B[kk]); by[nt] = to_tf32(B[kk + 4]);
            }
            #pragma unroll
            for (int mt = 0; mt < 4; mt++) {
                int r = wm * 64 + mt * 16 + g_;
                const float* X = st + X2_OFF + r * SROW;
                float x0 = to_tf32(X[kk]);
                float x1 = to_tf32(X[8 * SROW + kk]);
                float x2 = to_tf32(X[kk + 4]);
                float x3 = to_tf32(X[8 * SROW + kk + 4]);
                #pragma unroll
                for (int nt = 0; nt < 4; nt++)
                    MMA_TF32(acc[mt][nt], x0, x1, x2, x3, bx[nt], by[nt]);
            }
        }
        __syncthreads();
    }

    #pragma unroll
    for (int mt = 0; mt < 4; mt++) {
        int ra = row0 + wm * 64 + mt * 16 + g_;
        int rb = ra + 8;
        #pragma unroll
        for (int nt = 0; nt < 4; nt++) {
            int lcol = wn * 32 + nt * 8 + 2 * t_;
            int col = col0 + lcol;
            float br0 = sBr[lcol], br1 = sBr[lcol + 1];
            if (ra < NN)
                *(float2*)&out[(size_t)ra * DOUT + col] =
                    make_float2(acc[mt][nt][0] + br0, acc[mt][nt][1] + br1);
            if (rb < NN)
                *(float2*)&out[(size_t)rb * DOUT + col] =
                    make_float2(acc[mt][nt][2] + br0, acc[mt][nt][3] + br1);
        }
    }
}

// ---------------- combine (with inlined BN finalize): out = relu(pre*sc+sh)+out
__global__ __launch_bounds__(256) void k_combine(
    const float* __restrict__ gamma, const float* __restrict__ beta,
    float* __restrict__ out)
{
    __shared__ float sSc[DOUT], sSh[DOUT];
    {
        int j = threadIdx.x;          // 256 threads == DOUT
        const float invN = 1.0f / (float)NN;
        float mean = g_sum[j] * invN;
        float var = g_sqsum[j] * invN - mean * mean;
        float rstd = rsqrtf(var + BN_EPS);
        float sc = rstd * __ldg(&gamma[j]);
        sSc[j] = sc;
        sSh[j] = __ldg(&beta[j]) - mean * sc;
    }
    __syncthreads();

    size_t i = (size_t)blockIdx.x * blockDim.x + threadIdx.x;
    size_t stride = (size_t)gridDim.x * blockDim.x;
    const size_t total = (size_t)NN * (DOUT / 4);
    const float4* pre4 = (const float4*)g_pre;
    float4* out4 = (float4*)out;
    for (size_t j = i; j < total; j += stride) {
        int col4 = (int)(j & 63) * 4;
        float4 pv = pre4[j];
        float4 ov = out4[j];
        float4 sc = *(const float4*)&sSc[col4];
        float4 sh = *(const float4*)&sSh[col4];
        float4 o;
        o.x = fmaxf(pv.x * sc.x + sh.x, 0.f) + ov.x;
        o.y = fmaxf(pv.y * sc.y + sh.y, 0.f) + ov.y;
        o.z = fmaxf(pv.z * sc.z + sh.z, 0.f) + ov.z;
        o.w = fmaxf(pv.w * sc.w + sh.w, 0.f) + ov.w;
        out4[j] = o;
    }
}

// ---------------- launch ------------------------------------------------------
extern "C" void kernel_launch(void* const* d_in, const int* in_sizes, int n_in,
                              void* d_out, int out_size) {
    const float* x     = (const float*)d_in[0];
    const void*  ei    = d_in[1];
    const float* Wl    = (const float*)d_in[2];
    // d_in[3] = b_l — absorbed by BatchNorm, unused
    const float* Wr    = (const float*)d_in[4];
    const float* Wres  = (const float*)d_in[5];
    const float* bres  = (const float*)d_in[6];
    const float* gamma = (const float*)d_in[7];
    const float* beta  = (const float*)d_in[8];
    float* out = (float*)d_out;

    cudaFuncSetAttribute(k_mma_pre, cudaFuncAttributeMaxDynamicSharedMemorySize, SM1_BYTES);
    cudaFuncSetAttribute(k_mma_id, cudaFuncAttributeMaxDynamicSharedMemorySize, SM2_BYTES);

    // second stream for the independent id-GEMM (event fork/join keeps one graph DAG).
    // Static: created once per process; host objects only — capture-safe.
    static cudaStream_t s2 = nullptr;
    static cudaEvent_t ev_fork = nullptr, ev_id = nullptr;
    if (!s2) {
        cudaStreamCreateWithFlags(&s2, cudaStreamNonBlocking);
        cudaEventCreateWithFlags(&ev_fork, cudaEventDisableTiming);
        cudaEventCreateWithFlags(&ev_id, cudaEventDisableTiming);
    }

    dim3 g1(NTILES, 2);

    cudaEventRecord(ev_fork, 0);
    cudaStreamWaitEvent(s2, ev_fork, 0);
    k_mma_id<<<g1, 256, SM2_BYTES, s2>>>(x, Wres, bres, out);
    cudaEventRecord(ev_id, s2);

    k_init<<<64, 1024>>>((const unsigned*)ei);
    k_hist<<<(EE / 4 + 255) / 256, 256>>>(ei);
    k_scan1<<<NBLK, SCAN_BLK>>>();
    k_scan3<<<(NN + 255) / 256, 256>>>();
    k_fill<<<(EE + 255) / 256, 256>>>(ei);
    k_gather<<<(NN * 32 + 255) / 256, 256>>>(x);
    k_mma_pre<<<g1, 256, SM1_BYTES>>>(x, Wl, Wr);

    cudaStreamWaitEvent(0, ev_id, 0);
    k_combine<<<2048, 256>>>(gamma, beta, out);
}